// round 14
// baseline (speedup 1.0000x reference)
#include <cuda_runtime.h>

#define N_TOTAL 10000
#define D 128
#define BSZ 100
#define FEAT 3072
#define TOPK 50
#define NTILES 79          // ceil(10000/128)
#define TRI_BLOCKS (NTILES * (NTILES + 1) / 2)
#define CAP 2048           // candidate buffer capacity in topk
#define NF4 2500           // N_TOTAL/4

#define SC_ALD 68          // As leading dim (floats), scores
#define SC_SMEM ((128 * SC_ALD + 64 * 132) * 4)   // 68608 B dynamic smem

// ---------------- scratch (device globals: no allocation allowed) ----------
__device__ float g_x[(size_t)N_TOTAL * D];                 // pre-BN linear out
__device__ float g_y[(size_t)N_TOTAL * D];                 // -2 * out * sw
__device__ float g_a[N_TOTAL];                             // sum_k sw*out^2
__device__ float g_scores[(size_t)N_TOTAL * N_TOTAL];      // 400 MB scratch

// ---------------- f32x2 helpers (packed FFMA2) -----------------------------
__device__ __forceinline__ unsigned long long pack2(float x, float y) {
    unsigned long long r;
    asm("mov.b64 %0, {%1, %2};" : "=l"(r) : "f"(x), "f"(y));
    return r;
}
__device__ __forceinline__ float2 unpack2(unsigned long long v) {
    float x, y;
    asm("mov.b64 {%0, %1}, %2;" : "=f"(x), "=f"(y) : "l"(v));
    return make_float2(x, y);
}
__device__ __forceinline__ void fma2(unsigned long long& c,
                                     unsigned long long a,
                                     unsigned long long b) {
    asm("fma.rn.f32x2 %0, %1, %2, %3;" : "=l"(c) : "l"(a), "l"(b), "l"(c));
}

// ===========================================================================
// Kernel 1: x = inputs @ W1^T + b1      (R9 structure, K-chunk 64)
// ===========================================================================
__global__ void gemm1_kernel(const float* __restrict__ A,
                             const float* __restrict__ W,
                             const float* __restrict__ b1) {
    __shared__ __align__(16) float As[32][SC_ALD];
    __shared__ __align__(16) float Bs[64][132];

    const int tid = threadIdx.x;
    const int mbase = blockIdx.x * 32;
    const int t = tid & 15;
    const int r0 = (tid >> 4) * 4;

    unsigned long long acc[4][4];
#pragma unroll
    for (int i = 0; i < 4; ++i)
#pragma unroll
        for (int u = 0; u < 4; ++u) acc[i][u] = 0ULL;

    const int lr = tid >> 3;          // 0..15
    const int lk = (tid & 7) * 4;     // 0..28
    const int arow = tid >> 2;        // 0..31
    const int ak0 = (tid & 3) * 16;   // 0,16,32,48

    for (int kc = 0; kc < FEAT; kc += 64) {
        // A: 32 rows x 64 k (each thread 4 float4)
        {
            int m = mbase + arow;
#pragma unroll
            for (int q = 0; q < 4; ++q) {
                int k = ak0 + 4 * q;
                float4 v = make_float4(0.f, 0.f, 0.f, 0.f);
                if (m < N_TOTAL)
                    v = *(const float4*)&A[(size_t)m * FEAT + kc + k];
                *(float4*)&As[arow][k] = v;
            }
        }
        // B: 128 n-rows x 64 k, transposed store
#pragma unroll
        for (int it = 0; it < 8; ++it) {
            int n = it * 16 + lr;
#pragma unroll
            for (int kh = 0; kh < 64; kh += 32) {
                float4 v = *(const float4*)&W[(size_t)n * FEAT + kc + kh + lk];
                Bs[kh + lk + 0][n] = v.x;
                Bs[kh + lk + 1][n] = v.y;
                Bs[kh + lk + 2][n] = v.z;
                Bs[kh + lk + 3][n] = v.w;
            }
        }
        __syncthreads();

#pragma unroll 8
        for (int kk = 0; kk < 64; ++kk) {
            unsigned long long bv[4];
#pragma unroll
            for (int u = 0; u < 4; ++u)
                bv[u] = *(const unsigned long long*)&Bs[kk][2 * t + 32 * u];
#pragma unroll
            for (int i = 0; i < 4; ++i) {
                float av = As[r0 + i][kk];
                unsigned long long ap = pack2(av, av);
#pragma unroll
                for (int u = 0; u < 4; ++u) fma2(acc[i][u], ap, bv[u]);
            }
        }
        __syncthreads();
    }

#pragma unroll
    for (int i = 0; i < 4; ++i) {
        int m = mbase + r0 + i;
        if (m < N_TOTAL) {
#pragma unroll
            for (int u = 0; u < 4; ++u) {
                int col = 2 * t + 32 * u;
                float2 c = unpack2(acc[i][u]);
                c.x += b1[col];
                c.y += b1[col + 1];
                *(float2*)&g_x[(size_t)m * D + col] = c;
            }
        }
    }
}

// ===========================================================================
// Kernel 2: BatchNorm per micro-batch of 100 rows + fused y/a computation.
// ===========================================================================
__global__ void bn_kernel(const float* __restrict__ gamma,
                          const float* __restrict__ beta,
                          const float* __restrict__ sw,
                          float* __restrict__ outp) {
    const int b = blockIdx.x;
    const int c = threadIdx.x;
    __shared__ float arow[BSZ];
    if (c < BSZ) arow[c] = 0.f;

    const float* xb = g_x + (size_t)b * BSZ * D + c;
    float s = 0.f, s2 = 0.f;
    for (int r = 0; r < BSZ; ++r) {
        float v = xb[(size_t)r * D];
        s += v;
        s2 += v * v;
    }
    float mean = s * (1.f / BSZ);
    float var = s2 * (1.f / BSZ) - mean * mean;
    float rs = rsqrtf(var + 1e-5f);
    float g = gamma[c], be = beta[c], w = sw[c];
    __syncthreads();

    const int lane = c & 31;
    for (int r = 0; r < BSZ; ++r) {
        float v = xb[(size_t)r * D];
        float o = (v - mean) * rs * g + be;
        size_t idx = (size_t)(b * BSZ + r) * D + c;
        outp[idx] = o;
        g_y[idx] = -2.f * o * w;
        float contrib = w * o * o;
#pragma unroll
        for (int off = 16; off; off >>= 1)
            contrib += __shfl_down_sync(0xffffffffu, contrib, off);
        if (lane == 0) atomicAdd(&arow[r], contrib);
    }
    __syncthreads();
    if (c < BSZ) g_a[b * BSZ + c] = arow[c];
}

// ===========================================================================
// Kernel 3: scores[i,j] = relu(a_i + a_j + sb + y_i . out_j)   (SYMMETRIC)
// R9 structure with K-chunk 64 (2 chunks, 4 barriers) and 68.6KB dynamic
// smem -> 2 CTAs/SM residency preserved. Inner loop identical to R9.
// ===========================================================================
__global__ void __launch_bounds__(256) scores_kernel(const float* __restrict__ O,
                                                     const float* __restrict__ sbp) {
    extern __shared__ __align__(16) float smem[];
    float (*As)[SC_ALD] = (float(*)[SC_ALD])smem;              // 128 x 68
    float (*Bs)[132] = (float(*)[132])(smem + 128 * SC_ALD);   // 64 x 132

    int tt = blockIdx.x;
    int bi = 0;
    while (tt >= NTILES - bi) { tt -= NTILES - bi; ++bi; }
    const int bj = bi + tt;

    const int tid = threadIdx.x;
    const int ibase = bi * 128;
    const int jbase = bj * 128;
    const int t = tid & 15;                      // column group
    const int r0 = (tid >> 4) * 8;

    unsigned long long acc[8][4];
#pragma unroll
    for (int i = 0; i < 8; ++i)
#pragma unroll
        for (int u = 0; u < 4; ++u) acc[i][u] = 0ULL;

    const int lr = tid >> 3;          // 0..31
    const int lk = (tid & 7) * 4;     // 0..28
    const int arow = tid >> 1;        // 0..127
    const int ak0 = (tid & 1) * 32;   // 0,32

    for (int kc = 0; kc < D; kc += 64) {
        // A: 128 rows x 64 k (each thread 8 float4)
        {
            int m = ibase + arow;
#pragma unroll
            for (int q = 0; q < 8; ++q) {
                int k = ak0 + 4 * q;
                float4 v = make_float4(0.f, 0.f, 0.f, 0.f);
                if (m < N_TOTAL)
                    v = *(const float4*)&g_y[(size_t)m * D + kc + k];
                *(float4*)&As[arow][k] = v;
            }
        }
        // B: 128 j-rows x 64 k, transposed
#pragma unroll
        for (int it = 0; it < 4; ++it) {
            int colg = it * 32 + lr;
            int j = jbase + colg;
#pragma unroll
            for (int kh = 0; kh < 64; kh += 32) {
                float4 v = make_float4(0.f, 0.f, 0.f, 0.f);
                if (j < N_TOTAL)
                    v = *(const float4*)&O[(size_t)j * D + kc + kh + lk];
                Bs[kh + lk + 0][colg] = v.x;
                Bs[kh + lk + 1][colg] = v.y;
                Bs[kh + lk + 2][colg] = v.z;
                Bs[kh + lk + 3][colg] = v.w;
            }
        }
        __syncthreads();

#pragma unroll 4
        for (int kk = 0; kk < 64; ++kk) {
            unsigned long long bv[4];
#pragma unroll
            for (int u = 0; u < 4; ++u)
                bv[u] = *(const unsigned long long*)&Bs[kk][2 * t + 32 * u];
#pragma unroll
            for (int i = 0; i < 8; ++i) {
                float av = As[r0 + i][kk];
                unsigned long long ap = pack2(av, av);
#pragma unroll
                for (int u = 0; u < 4; ++u) fma2(acc[i][u], ap, bv[u]);
            }
        }
        __syncthreads();
    }

    const float sbv = *sbp;
    float ai[8], aj[8];
#pragma unroll
    for (int i = 0; i < 8; ++i) {
        int gi = ibase + r0 + i;
        ai[i] = (gi < N_TOTAL) ? g_a[gi] : 0.f;
    }
#pragma unroll
    for (int u = 0; u < 4; ++u) {
#pragma unroll
        for (int q = 0; q < 2; ++q) {
            int gj = jbase + 2 * t + 32 * u + q;
            aj[2 * u + q] = (gj < N_TOTAL) ? g_a[gj] : 0.f;
        }
    }

    // sv[i][2u+q] corresponds to global column jbase + 2t + 32u + q
    float sv[8][8];
#pragma unroll
    for (int i = 0; i < 8; ++i) {
        float base = ai[i] + sbv;
#pragma unroll
        for (int u = 0; u < 4; ++u) {
            float2 c = unpack2(acc[i][u]);
            sv[i][2 * u]     = fmaxf(base + aj[2 * u] + c.x, 0.f);
            sv[i][2 * u + 1] = fmaxf(base + aj[2 * u + 1] + c.y, 0.f);
        }
    }

    const bool full_i = (ibase + 128 <= N_TOTAL);
    const bool full_j = (jbase + 128 <= N_TOTAL);

    if (full_i && full_j) {
#pragma unroll
        for (int i = 0; i < 8; ++i) {
            size_t rbase = (size_t)(ibase + r0 + i) * N_TOTAL + jbase + 2 * t;
#pragma unroll
            for (int u = 0; u < 4; ++u)
                *(float2*)&g_scores[rbase + 32 * u] =
                    make_float2(sv[i][2 * u], sv[i][2 * u + 1]);
        }
        if (bi != bj) {
#pragma unroll
            for (int u = 0; u < 4; ++u) {
#pragma unroll
                for (int q = 0; q < 2; ++q) {
                    int jc = jbase + 2 * t + 32 * u + q;
                    size_t base = (size_t)jc * N_TOTAL + ibase + r0;
                    int v = 2 * u + q;
                    *(float4*)&g_scores[base] =
                        make_float4(sv[0][v], sv[1][v], sv[2][v], sv[3][v]);
                    *(float4*)&g_scores[base + 4] =
                        make_float4(sv[4][v], sv[5][v], sv[6][v], sv[7][v]);
                }
            }
        }
    } else {
#pragma unroll
        for (int i = 0; i < 8; ++i) {
            int gi = ibase + r0 + i;
            if (gi >= N_TOTAL) continue;
#pragma unroll
            for (int u = 0; u < 4; ++u) {
#pragma unroll
                for (int q = 0; q < 2; ++q) {
                    int gj = jbase + 2 * t + 32 * u + q;
                    if (gj >= N_TOTAL) continue;
                    g_scores[(size_t)gi * N_TOTAL + gj] = sv[i][2 * u + q];
                    if (bi != bj)
                        g_scores[(size_t)gj * N_TOTAL + gi] = sv[i][2 * u + q];
                }
            }
        }
    }
}

// ===========================================================================
// Kernel 4: per-row exact top-50 — single-pass threshold buffer (R6 proven).
// ===========================================================================
__global__ void __launch_bounds__(256) topk_kernel(float* __restrict__ S) {
    __shared__ float bval[CAP];
    __shared__ int   bidx[CAP];
    __shared__ unsigned hist[256];
    __shared__ int idxbuf[64];
    __shared__ int eqbuf[256];
    __shared__ float vbuf[TOPK];
    __shared__ float ebuf[TOPK];
    __shared__ int bcount, cnt_gt, cnt_eq;
    __shared__ unsigned sh_sel;
    __shared__ int sh_krem, sh_binc;
    __shared__ unsigned sh_thr;
    __shared__ float sh_inv;

    const int row = blockIdx.x;
    const int tid = threadIdx.x;
    const int lane = tid & 31;

    const float* rowp = g_scores + (size_t)row * N_TOTAL;
    const float4* rp4 = (const float4*)rowp;
    float4* sp4 = (float4*)(S + (size_t)row * N_TOTAL);

    if (tid == 0) { bcount = 0; cnt_gt = 0; cnt_eq = 0; sh_thr = 0; }
    __syncthreads();

#define WARP_SELECT(ARR, KREM)                                                \
    if (tid < 32) {                                                           \
        unsigned h[8], ls[8];                                                 \
        int b0 = lane * 8;                                                    \
        _Pragma("unroll")                                                     \
        for (int j = 0; j < 8; ++j) h[j] = (ARR)[b0 + j];                     \
        ls[7] = h[7];                                                         \
        _Pragma("unroll")                                                     \
        for (int j = 6; j >= 0; --j) ls[j] = ls[j + 1] + h[j];                \
        unsigned tot = ls[0];                                                 \
        unsigned ss = tot;                                                    \
        _Pragma("unroll")                                                     \
        for (int off = 1; off < 32; off <<= 1) {                              \
            unsigned o = __shfl_down_sync(0xffffffffu, ss, off);              \
            if (lane + off < 32) ss += o;                                     \
        }                                                                     \
        unsigned above = ss - tot;                                            \
        int best = -1;                                                        \
        _Pragma("unroll")                                                     \
        for (int j = 7; j >= 0; --j)                                          \
            if (best < 0 && above + ls[j] >= (unsigned)(KREM)) best = j;      \
        unsigned m = __ballot_sync(0xffffffffu, best >= 0);                   \
        int hi = 31 - __clz((int)m);                                          \
        if (lane == hi) {                                                     \
            unsigned Sb = above + ls[best];                                   \
            sh_sel = (unsigned)(b0 + best);                                   \
            sh_binc = (int)h[best];                                           \
            sh_krem = (KREM) - (int)(Sb - h[best]);                           \
        }                                                                     \
    }

#define EXACT_SELECT(CNT, KINIT, PREFIX, KREM)                                \
    {                                                                         \
        (PREFIX) = 0; (KREM) = (KINIT);                                       \
        const int SHS[4] = {24, 16, 8, 0};                                    \
        const unsigned HMS[4] = {0u, 0xFF000000u, 0xFFFF0000u, 0xFFFFFF00u};  \
        for (int ps = 0; ps < 4; ++ps) {                                      \
            hist[tid] = 0;                                                    \
            __syncthreads();                                                  \
            for (int i = tid; i < (CNT); i += 256) {                          \
                unsigned b = __float_as_uint(bval[i]);                        \
                if ((b & HMS[ps]) == ((PREFIX) & HMS[ps]))                    \
                    atomicAdd(&hist[(b >> SHS[ps]) & 255u], 1u);              \
            }                                                                 \
            __syncthreads();                                                  \
            WARP_SELECT(hist, (KREM))                                         \
            __syncthreads();                                                  \
            (PREFIX) |= sh_sel << SHS[ps];                                    \
            (KREM) = sh_krem;                                                 \
            __syncthreads();                                                  \
        }                                                                     \
    }

#define PUSH(V, IDX)                                                          \
    {                                                                         \
        unsigned b_ = __float_as_uint(V);                                     \
        if (b_ >= thr) {                                                      \
            unsigned mk = __activemask();                                     \
            int ldr = __ffs(mk) - 1;                                          \
            int rk = __popc(mk & ((1u << lane) - 1));                         \
            int bs;                                                           \
            if (lane == ldr) bs = atomicAdd(&bcount, __popc(mk));             \
            bs = __shfl_sync(mk, bs, ldr);                                    \
            int p_ = bs + rk;                                                 \
            if (p_ < CAP) { bval[p_] = (V); bidx[p_] = (IDX); }               \
        }                                                                     \
    }

    unsigned thr = 0;
    const float4 z = make_float4(0.f, 0.f, 0.f, 0.f);

    for (int chunk = 0; chunk < 10; ++chunk) {
        if (bcount > CAP - 1024) {
            unsigned pfx; int kr;
            EXACT_SELECT(bcount, TOPK, pfx, kr)
            (void)kr;
            const int cnt = bcount;
            float mv[8]; int mi[8]; int mc = 0;
            for (int i = tid; i < cnt; i += 256) {
                unsigned b = __float_as_uint(bval[i]);
                if (b >= pfx) { mv[mc] = bval[i]; mi[mc] = bidx[i]; ++mc; }
            }
            __syncthreads();
            if (tid == 0) { bcount = 0; sh_thr = pfx; }
            __syncthreads();
            for (int j = 0; j < mc; ++j) {
                int p = atomicAdd(&bcount, 1);
                bval[p] = mv[j]; bidx[p] = mi[j];
            }
            __syncthreads();
            thr = sh_thr;
        }

        int i4 = chunk * 256 + tid;
        if (i4 < NF4) {
            float4 val = rp4[i4];
            sp4[i4] = z;
            PUSH(val.x, 4 * i4 + 0)
            PUSH(val.y, 4 * i4 + 1)
            PUSH(val.z, 4 * i4 + 2)
            PUSH(val.w, 4 * i4 + 3)
        }
        __syncthreads();
    }

    const int nc = bcount;
    unsigned prefix; int krem;
    EXACT_SELECT(nc, TOPK, prefix, krem)

    for (int i = tid; i < nc; i += 256) {
        unsigned b = __float_as_uint(bval[i]);
        if (b > prefix) {
            int p = atomicAdd(&cnt_gt, 1);
            idxbuf[p] = bidx[i];
        } else if (b == prefix) {
            int p = atomicAdd(&cnt_eq, 1);
            if (p < 256) eqbuf[p] = bidx[i];
        }
    }
    __syncthreads();

    if (tid == 0) {
        int n = cnt_gt;
        int need = TOPK - n;
        if (cnt_eq <= 256) {
            for (int t2 = 0; t2 < need; ++t2) {
                int best = 0x7fffffff, bj2 = 0;
                for (int j2 = 0; j2 < cnt_eq; ++j2) {
                    int vv = eqbuf[j2];
                    if (vv < best) { best = vv; bj2 = j2; }
                }
                idxbuf[n++] = best;
                eqbuf[bj2] = 0x7fffffff;
            }
        } else {
            for (int t2 = 0; t2 < need; ++t2) {
                int best = 0x7fffffff, bj2 = -1;
                for (int i = 0; i < nc; ++i) {
                    if (__float_as_uint(bval[i]) == prefix && bidx[i] < best) {
                        best = bidx[i]; bj2 = i;
                    }
                }
                idxbuf[n++] = best;
                if (bj2 >= 0) bidx[bj2] = 0x7fffffff;
            }
        }
    }
    __syncthreads();

    if (tid < TOPK) vbuf[tid] = rowp[idxbuf[tid]];
    __syncthreads();
    if (tid == 0) {
        float mx = -1e30f;
        for (int t2 = 0; t2 < TOPK; ++t2) mx = fmaxf(mx, vbuf[t2]);
        float ssum = 0.f;
        for (int t2 = 0; t2 < TOPK; ++t2) {
            float e = expf(vbuf[t2] - mx);
            ebuf[t2] = e;
            ssum += e;
        }
        sh_inv = 1.f / ssum;
    }
    __syncthreads();
    if (tid < TOPK)
        S[(size_t)row * N_TOTAL + idxbuf[tid]] = ebuf[tid] * sh_inv;

#undef PUSH
#undef EXACT_SELECT
#undef WARP_SELECT
}

// ===========================================================================
extern "C" void kernel_launch(void* const* d_in, const int* in_sizes, int n_in,
                              void* d_out, int out_size) {
    const float* inputs = (const float*)d_in[0];
    const float* W1     = (const float*)d_in[1];
    const float* b1     = (const float*)d_in[2];
    const float* gamma  = (const float*)d_in[3];
    const float* beta   = (const float*)d_in[4];
    const float* sw     = (const float*)d_in[5];
    const float* sb     = (const float*)d_in[6];

    float* outp = (float*)d_out;                       // [10000,128] outputs
    float* Sp   = outp + (size_t)N_TOTAL * D;          // [10000,10000] S

    cudaFuncSetAttribute(scores_kernel,
                         cudaFuncAttributeMaxDynamicSharedMemorySize, SC_SMEM);

    gemm1_kernel<<<(N_TOTAL + 31) / 32, 128>>>(inputs, W1, b1);
    bn_kernel<<<N_TOTAL / BSZ, D>>>(gamma, beta, sw, outp);
    scores_kernel<<<TRI_BLOCKS, 256, SC_SMEM>>>(outp, sb);
    topk_kernel<<<N_TOTAL, 256>>>(Sp);
}

// round 15
// speedup vs baseline: 1.1740x; 1.1740x over previous
#include <cuda_runtime.h>
#include <cstdint>

#define N_TOTAL 10000
#define D 128
#define BSZ 100
#define FEAT 3072
#define TOPK 50
#define NTILES 79          // ceil(10000/128)
#define TRI_BLOCKS (NTILES * (NTILES + 1) / 2)
#define CAP 2048           // candidate buffer capacity in topk
#define NF4 2500           // N_TOTAL/4

#define KC 32              // scores k-chunk
#define SLD 36             // smem row stride (uints) for operand arrays
#define SC_SMEM (4 * 128 * SLD * 4)   // 73728 B dynamic smem

// ---------------- scratch (device globals: no allocation allowed) ----------
__device__ float g_x[(size_t)N_TOTAL * D];                 // pre-BN linear out
__device__ float g_y[(size_t)N_TOTAL * D];                 // -2 * out * sw
__device__ float g_a[N_TOTAL];                             // sum_k sw*out^2
__device__ float g_scores[(size_t)N_TOTAL * N_TOTAL];      // 400 MB scratch

// ---------------- f32x2 helpers (packed FFMA2) -----------------------------
__device__ __forceinline__ unsigned long long pack2(float x, float y) {
    unsigned long long r;
    asm("mov.b64 %0, {%1, %2};" : "=l"(r) : "f"(x), "f"(y));
    return r;
}
__device__ __forceinline__ float2 unpack2(unsigned long long v) {
    float x, y;
    asm("mov.b64 {%0, %1}, %2;" : "=f"(x), "=f"(y) : "l"(v));
    return make_float2(x, y);
}
__device__ __forceinline__ void fma2(unsigned long long& c,
                                     unsigned long long a,
                                     unsigned long long b) {
    asm("fma.rn.f32x2 %0, %1, %2, %3;" : "=l"(c) : "l"(a), "l"(b), "l"(c));
}

// ---------------- tf32 helpers ----------------------------------------------
__device__ __forceinline__ unsigned tf32_of(float x) {
    unsigned r;
    asm("cvt.rna.tf32.f32 %0, %1;" : "=r"(r) : "f"(x));
    return r;
}
__device__ __forceinline__ void mma_tf32(float* c, const unsigned* a,
                                         const unsigned* b) {
    asm volatile(
        "mma.sync.aligned.m16n8k8.row.col.f32.tf32.tf32.f32 "
        "{%0,%1,%2,%3}, {%4,%5,%6,%7}, {%8,%9}, {%0,%1,%2,%3};"
        : "+f"(c[0]), "+f"(c[1]), "+f"(c[2]), "+f"(c[3])
        : "r"(a[0]), "r"(a[1]), "r"(a[2]), "r"(a[3]), "r"(b[0]), "r"(b[1]));
}

// ===========================================================================
// Kernel 1: x = inputs @ W1^T + b1      (R9 proven version)
// ===========================================================================
__global__ void gemm1_kernel(const float* __restrict__ A,
                             const float* __restrict__ W,
                             const float* __restrict__ b1) {
    __shared__ __align__(16) float As[32][36];
    __shared__ __align__(16) float Bs[32][132];

    const int tid = threadIdx.x;
    const int mbase = blockIdx.x * 32;
    const int t = tid & 15;
    const int r0 = (tid >> 4) * 4;

    unsigned long long acc[4][4];
#pragma unroll
    for (int i = 0; i < 4; ++i)
#pragma unroll
        for (int u = 0; u < 4; ++u) acc[i][u] = 0ULL;

    const int lr = tid >> 3;
    const int lk = (tid & 7) * 4;

    for (int kc = 0; kc < FEAT; kc += 32) {
#pragma unroll
        for (int it = 0; it < 2; ++it) {
            int m = mbase + it * 16 + lr;
            float4 v = make_float4(0.f, 0.f, 0.f, 0.f);
            if (m < N_TOTAL)
                v = *(const float4*)&A[(size_t)m * FEAT + kc + lk];
            *(float4*)&As[it * 16 + lr][lk] = v;
        }
#pragma unroll
        for (int it = 0; it < 8; ++it) {
            int n = it * 16 + lr;
            float4 v = *(const float4*)&W[(size_t)n * FEAT + kc + lk];
            Bs[lk + 0][n] = v.x;
            Bs[lk + 1][n] = v.y;
            Bs[lk + 2][n] = v.z;
            Bs[lk + 3][n] = v.w;
        }
        __syncthreads();

#pragma unroll 8
        for (int kk = 0; kk < 32; ++kk) {
            unsigned long long bv[4];
#pragma unroll
            for (int u = 0; u < 4; ++u)
                bv[u] = *(const unsigned long long*)&Bs[kk][2 * t + 32 * u];
#pragma unroll
            for (int i = 0; i < 4; ++i) {
                float av = As[r0 + i][kk];
                unsigned long long ap = pack2(av, av);
#pragma unroll
                for (int u = 0; u < 4; ++u) fma2(acc[i][u], ap, bv[u]);
            }
        }
        __syncthreads();
    }

#pragma unroll
    for (int i = 0; i < 4; ++i) {
        int m = mbase + r0 + i;
        if (m < N_TOTAL) {
#pragma unroll
            for (int u = 0; u < 4; ++u) {
                int col = 2 * t + 32 * u;
                float2 c = unpack2(acc[i][u]);
                c.x += b1[col];
                c.y += b1[col + 1];
                *(float2*)&g_x[(size_t)m * D + col] = c;
            }
        }
    }
}

// ===========================================================================
// Kernel 2: BatchNorm per micro-batch of 100 rows + fused y/a computation.
// ===========================================================================
__global__ void bn_kernel(const float* __restrict__ gamma,
                          const float* __restrict__ beta,
                          const float* __restrict__ sw,
                          float* __restrict__ outp) {
    const int b = blockIdx.x;
    const int c = threadIdx.x;
    __shared__ float arow[BSZ];
    if (c < BSZ) arow[c] = 0.f;

    const float* xb = g_x + (size_t)b * BSZ * D + c;
    float s = 0.f, s2 = 0.f;
    for (int r = 0; r < BSZ; ++r) {
        float v = xb[(size_t)r * D];
        s += v;
        s2 += v * v;
    }
    float mean = s * (1.f / BSZ);
    float var = s2 * (1.f / BSZ) - mean * mean;
    float rs = rsqrtf(var + 1e-5f);
    float g = gamma[c], be = beta[c], w = sw[c];
    __syncthreads();

    const int lane = c & 31;
    for (int r = 0; r < BSZ; ++r) {
        float v = xb[(size_t)r * D];
        float o = (v - mean) * rs * g + be;
        size_t idx = (size_t)(b * BSZ + r) * D + c;
        outp[idx] = o;
        g_y[idx] = -2.f * o * w;
        float contrib = w * o * o;
#pragma unroll
        for (int off = 16; off; off >>= 1)
            contrib += __shfl_down_sync(0xffffffffu, contrib, off);
        if (lane == 0) atomicAdd(&arow[r], contrib);
    }
    __syncthreads();
    if (c < BSZ) g_a[b * BSZ + c] = arow[c];
}

// ===========================================================================
// Kernel 3: scores via mma.sync TF32 (3xTF32 split: hh + hl + lh).
// Tile 128x128, triangular launch, 8 warps as 2(M) x 4(N); each warp owns a
// 64x32 region = 4 m-tiles(16) x 4 n-tiles(8). K in 4 chunks of 32.
// Operands pre-split to tf32 hi/lo in smem ([128][36] K-major, conflict-free
// fragment loads). Accuracy ~fp32 (error ~1e-7 rel) -> exact topk unchanged.
// ===========================================================================
__global__ void __launch_bounds__(256, 2)
scores_kernel(const float* __restrict__ O, const float* __restrict__ sbp) {
    extern __shared__ __align__(16) unsigned smem_u[];
    unsigned (*Ah)[SLD] = (unsigned(*)[SLD])smem_u;                 // [m][k]
    unsigned (*Al)[SLD] = (unsigned(*)[SLD])(smem_u + 128 * SLD);
    unsigned (*Bh)[SLD] = (unsigned(*)[SLD])(smem_u + 2 * 128 * SLD); // [n][k]
    unsigned (*Bl)[SLD] = (unsigned(*)[SLD])(smem_u + 3 * 128 * SLD);

    int tt = blockIdx.x;
    int bi = 0;
    while (tt >= NTILES - bi) { tt -= NTILES - bi; ++bi; }
    const int bj = bi + tt;

    const int tid = threadIdx.x;
    const int lane = tid & 31;
    const int wid = tid >> 5;
    const int warp_m = wid & 1;        // 0..1  (64-row groups)
    const int warp_n = wid >> 1;       // 0..3  (32-col groups)
    const int g = lane >> 2;           // groupID 0..7
    const int tig = lane & 3;          // thread-in-group 0..3

    const int ibase = bi * 128;
    const int jbase = bj * 128;

    float acc[4][4][4];
#pragma unroll
    for (int mt = 0; mt < 4; ++mt)
#pragma unroll
        for (int nt = 0; nt < 4; ++nt)
#pragma unroll
            for (int r = 0; r < 4; ++r) acc[mt][nt][r] = 0.f;

    const int frow = tid >> 1;               // 0..127 (fill row)
    const int fc0 = (tid & 1) * 16;          // 0 or 16

    for (int kc = 0; kc < D; kc += KC) {
        // ---- fill: split A (g_y) and B (O) rows into tf32 hi/lo ----
        {
            int mrow = ibase + frow;
            int jrow = jbase + frow;
#pragma unroll
            for (int q = 0; q < 4; ++q) {
                int k = fc0 + 4 * q;
                float4 va = make_float4(0.f, 0.f, 0.f, 0.f);
                float4 vb = make_float4(0.f, 0.f, 0.f, 0.f);
                if (mrow < N_TOTAL)
                    va = *(const float4*)&g_y[(size_t)mrow * D + kc + k];
                if (jrow < N_TOTAL)
                    vb = *(const float4*)&O[(size_t)jrow * D + kc + k];
                const float ea[4] = {va.x, va.y, va.z, va.w};
                const float eb[4] = {vb.x, vb.y, vb.z, vb.w};
#pragma unroll
                for (int e = 0; e < 4; ++e) {
                    unsigned h = tf32_of(ea[e]);
                    Ah[frow][k + e] = h;
                    Al[frow][k + e] = tf32_of(ea[e] - __uint_as_float(h));
                    unsigned hb = tf32_of(eb[e]);
                    Bh[frow][k + e] = hb;
                    Bl[frow][k + e] = tf32_of(eb[e] - __uint_as_float(hb));
                }
            }
        }
        __syncthreads();

        // ---- 4 k-steps of 8 ----
#pragma unroll
        for (int ks = 0; ks < 4; ++ks) {
            const int k0 = ks * 8;
            unsigned bh[4][2], bl[4][2];
#pragma unroll
            for (int nt = 0; nt < 4; ++nt) {
                int n = warp_n * 32 + nt * 8 + g;
                bh[nt][0] = Bh[n][k0 + tig];
                bh[nt][1] = Bh[n][k0 + tig + 4];
                bl[nt][0] = Bl[n][k0 + tig];
                bl[nt][1] = Bl[n][k0 + tig + 4];
            }
#pragma unroll
            for (int mt = 0; mt < 4; ++mt) {
                int m = warp_m * 64 + mt * 16;
                unsigned ah[4], al[4];
                ah[0] = Ah[m + g][k0 + tig];
                ah[1] = Ah[m + g + 8][k0 + tig];
                ah[2] = Ah[m + g][k0 + tig + 4];
                ah[3] = Ah[m + g + 8][k0 + tig + 4];
                al[0] = Al[m + g][k0 + tig];
                al[1] = Al[m + g + 8][k0 + tig];
                al[2] = Al[m + g][k0 + tig + 4];
                al[3] = Al[m + g + 8][k0 + tig + 4];
#pragma unroll
                for (int nt = 0; nt < 4; ++nt) {
                    mma_tf32(acc[mt][nt], ah, bh[nt]);   // hh
                    mma_tf32(acc[mt][nt], ah, bl[nt]);   // hl
                    mma_tf32(acc[mt][nt], al, bh[nt]);   // lh
                }
            }
        }
        __syncthreads();
    }

    // ---- epilogue: relu(a_i + a_j + sb + dot), store + mirror ----
    const float sbv = *sbp;
    const bool full = (ibase + 128 <= N_TOTAL) && (jbase + 128 <= N_TOTAL);

#pragma unroll
    for (int mt = 0; mt < 4; ++mt) {
        int gi0 = ibase + warp_m * 64 + mt * 16 + g;
        int gi1 = gi0 + 8;
        float ai0 = (gi0 < N_TOTAL) ? g_a[gi0] : 0.f;
        float ai1 = (gi1 < N_TOTAL) ? g_a[gi1] : 0.f;
#pragma unroll
        for (int nt = 0; nt < 4; ++nt) {
            int gj = jbase + warp_n * 32 + nt * 8 + 2 * tig;
            float aj0 = (gj < N_TOTAL) ? g_a[gj] : 0.f;
            float aj1 = (gj + 1 < N_TOTAL) ? g_a[gj + 1] : 0.f;
            const float* c = acc[mt][nt];
            float s00 = fmaxf(ai0 + aj0 + sbv + c[0], 0.f);
            float s01 = fmaxf(ai0 + aj1 + sbv + c[1], 0.f);
            float s10 = fmaxf(ai1 + aj0 + sbv + c[2], 0.f);
            float s11 = fmaxf(ai1 + aj1 + sbv + c[3], 0.f);
            if (full) {
                *(float2*)&g_scores[(size_t)gi0 * N_TOTAL + gj] =
                    make_float2(s00, s01);
                *(float2*)&g_scores[(size_t)gi1 * N_TOTAL + gj] =
                    make_float2(s10, s11);
                if (bi != bj) {
                    g_scores[(size_t)gj * N_TOTAL + gi0] = s00;
                    g_scores[(size_t)gj * N_TOTAL + gi1] = s10;
                    g_scores[(size_t)(gj + 1) * N_TOTAL + gi0] = s01;
                    g_scores[(size_t)(gj + 1) * N_TOTAL + gi1] = s11;
                }
            } else {
                if (gi0 < N_TOTAL && gj < N_TOTAL)
                    g_scores[(size_t)gi0 * N_TOTAL + gj] = s00;
                if (gi0 < N_TOTAL && gj + 1 < N_TOTAL)
                    g_scores[(size_t)gi0 * N_TOTAL + gj + 1] = s01;
                if (gi1 < N_TOTAL && gj < N_TOTAL)
                    g_scores[(size_t)gi1 * N_TOTAL + gj] = s10;
                if (gi1 < N_TOTAL && gj + 1 < N_TOTAL)
                    g_scores[(size_t)gi1 * N_TOTAL + gj + 1] = s11;
                if (bi != bj) {
                    if (gj < N_TOTAL && gi0 < N_TOTAL)
                        g_scores[(size_t)gj * N_TOTAL + gi0] = s00;
                    if (gj < N_TOTAL && gi1 < N_TOTAL)
                        g_scores[(size_t)gj * N_TOTAL + gi1] = s10;
                    if (gj + 1 < N_TOTAL && gi0 < N_TOTAL)
                        g_scores[(size_t)(gj + 1) * N_TOTAL + gi0] = s01;
                    if (gj + 1 < N_TOTAL && gi1 < N_TOTAL)
                        g_scores[(size_t)(gj + 1) * N_TOTAL + gi1] = s11;
                }
            }
        }
    }
}

// ===========================================================================
// Kernel 4: per-row exact top-50 — single-pass threshold buffer (R6 proven).
// ===========================================================================
__global__ void __launch_bounds__(256) topk_kernel(float* __restrict__ S) {
    __shared__ float bval[CAP];
    __shared__ int   bidx[CAP];
    __shared__ unsigned hist[256];
    __shared__ int idxbuf[64];
    __shared__ int eqbuf[256];
    __shared__ float vbuf[TOPK];
    __shared__ float ebuf[TOPK];
    __shared__ int bcount, cnt_gt, cnt_eq;
    __shared__ unsigned sh_sel;
    __shared__ int sh_krem, sh_binc;
    __shared__ unsigned sh_thr;
    __shared__ float sh_inv;

    const int row = blockIdx.x;
    const int tid = threadIdx.x;
    const int lane = tid & 31;

    const float* rowp = g_scores + (size_t)row * N_TOTAL;
    const float4* rp4 = (const float4*)rowp;
    float4* sp4 = (float4*)(S + (size_t)row * N_TOTAL);

    if (tid == 0) { bcount = 0; cnt_gt = 0; cnt_eq = 0; sh_thr = 0; }
    __syncthreads();

#define WARP_SELECT(ARR, KREM)                                                \
    if (tid < 32) {                                                           \
        unsigned h[8], ls[8];                                                 \
        int b0 = lane * 8;                                                    \
        _Pragma("unroll")                                                     \
        for (int j = 0; j < 8; ++j) h[j] = (ARR)[b0 + j];                     \
        ls[7] = h[7];                                                         \
        _Pragma("unroll")                                                     \
        for (int j = 6; j >= 0; --j) ls[j] = ls[j + 1] + h[j];                \
        unsigned tot = ls[0];                                                 \
        unsigned ss = tot;                                                    \
        _Pragma("unroll")                                                     \
        for (int off = 1; off < 32; off <<= 1) {                              \
            unsigned o = __shfl_down_sync(0xffffffffu, ss, off);              \
            if (lane + off < 32) ss += o;                                     \
        }                                                                     \
        unsigned above = ss - tot;                                            \
        int best = -1;                                                        \
        _Pragma("unroll")                                                     \
        for (int j = 7; j >= 0; --j)                                          \
            if (best < 0 && above + ls[j] >= (unsigned)(KREM)) best = j;      \
        unsigned m = __ballot_sync(0xffffffffu, best >= 0);                   \
        int hi = 31 - __clz((int)m);                                          \
        if (lane == hi) {                                                     \
            unsigned Sb = above + ls[best];                                   \
            sh_sel = (unsigned)(b0 + best);                                   \
            sh_binc = (int)h[best];                                           \
            sh_krem = (KREM) - (int)(Sb - h[best]);                           \
        }                                                                     \
    }

#define EXACT_SELECT(CNT, KINIT, PREFIX, KREM)                                \
    {                                                                         \
        (PREFIX) = 0; (KREM) = (KINIT);                                       \
        const int SHS[4] = {24, 16, 8, 0};                                    \
        const unsigned HMS[4] = {0u, 0xFF000000u, 0xFFFF0000u, 0xFFFFFF00u};  \
        for (int ps = 0; ps < 4; ++ps) {                                      \
            hist[tid] = 0;                                                    \
            __syncthreads();                                                  \
            for (int i = tid; i < (CNT); i += 256) {                          \
                unsigned b = __float_as_uint(bval[i]);                        \
                if ((b & HMS[ps]) == ((PREFIX) & HMS[ps]))                    \
                    atomicAdd(&hist[(b >> SHS[ps]) & 255u], 1u);              \
            }                                                                 \
            __syncthreads();                                                  \
            WARP_SELECT(hist, (KREM))                                         \
            __syncthreads();                                                  \
            (PREFIX) |= sh_sel << SHS[ps];                                    \
            (KREM) = sh_krem;                                                 \
            __syncthreads();                                                  \
        }                                                                     \
    }

#define PUSH(V, IDX)                                                          \
    {                                                                         \
        unsigned b_ = __float_as_uint(V);                                     \
        if (b_ >= thr) {                                                      \
            unsigned mk = __activemask();                                     \
            int ldr = __ffs(mk) - 1;                                          \
            int rk = __popc(mk & ((1u << lane) - 1));                         \
            int bs;                                                           \
            if (lane == ldr) bs = atomicAdd(&bcount, __popc(mk));             \
            bs = __shfl_sync(mk, bs, ldr);                                    \
            int p_ = bs + rk;                                                 \
            if (p_ < CAP) { bval[p_] = (V); bidx[p_] = (IDX); }               \
        }                                                                     \
    }

    unsigned thr = 0;
    const float4 z = make_float4(0.f, 0.f, 0.f, 0.f);

    for (int chunk = 0; chunk < 10; ++chunk) {
        if (bcount > CAP - 1024) {
            unsigned pfx; int kr;
            EXACT_SELECT(bcount, TOPK, pfx, kr)
            (void)kr;
            const int cnt = bcount;
            float mv[8]; int mi[8]; int mc = 0;
            for (int i = tid; i < cnt; i += 256) {
                unsigned b = __float_as_uint(bval[i]);
                if (b >= pfx) { mv[mc] = bval[i]; mi[mc] = bidx[i]; ++mc; }
            }
            __syncthreads();
            if (tid == 0) { bcount = 0; sh_thr = pfx; }
            __syncthreads();
            for (int j = 0; j < mc; ++j) {
                int p = atomicAdd(&bcount, 1);
                bval[p] = mv[j]; bidx[p] = mi[j];
            }
            __syncthreads();
            thr = sh_thr;
        }

        int i4 = chunk * 256 + tid;
        if (i4 < NF4) {
            float4 val = rp4[i4];
            sp4[i4] = z;
            PUSH(val.x, 4 * i4 + 0)
            PUSH(val.y, 4 * i4 + 1)
            PUSH(val.z, 4 * i4 + 2)
            PUSH(val.w, 4 * i4 + 3)
        }
        __syncthreads();
    }

    const int nc = bcount;
    unsigned prefix; int krem;
    EXACT_SELECT(nc, TOPK, prefix, krem)

    for (int i = tid; i < nc; i += 256) {
        unsigned b = __float_as_uint(bval[i]);
        if (b > prefix) {
            int p = atomicAdd(&cnt_gt, 1);
            idxbuf[p] = bidx[i];
        } else if (b == prefix) {
            int p = atomicAdd(&cnt_eq, 1);
            if (p < 256) eqbuf[p] = bidx[i];
        }
    }
    __syncthreads();

    if (tid == 0) {
        int n = cnt_gt;
        int need = TOPK - n;
        if (cnt_eq <= 256) {
            for (int t2 = 0; t2 < need; ++t2) {
                int best = 0x7fffffff, bj2 = 0;
                for (int j2 = 0; j2 < cnt_eq; ++j2) {
                    int vv = eqbuf[j2];
                    if (vv < best) { best = vv; bj2 = j2; }
                }
                idxbuf[n++] = best;
                eqbuf[bj2] = 0x7fffffff;
            }
        } else {
            for (int t2 = 0; t2 < need; ++t2) {
                int best = 0x7fffffff, bj2 = -1;
                for (int i = 0; i < nc; ++i) {
                    if (__float_as_uint(bval[i]) == prefix && bidx[i] < best) {
                        best = bidx[i]; bj2 = i;
                    }
                }
                idxbuf[n++] = best;
                if (bj2 >= 0) bidx[bj2] = 0x7fffffff;
            }
        }
    }
    __syncthreads();

    if (tid < TOPK) vbuf[tid] = rowp[idxbuf[tid]];
    __syncthreads();
    if (tid == 0) {
        float mx = -1e30f;
        for (int t2 = 0; t2 < TOPK; ++t2) mx = fmaxf(mx, vbuf[t2]);
        float ssum = 0.f;
        for (int t2 = 0; t2 < TOPK; ++t2) {
            float e = expf(vbuf[t2] - mx);
            ebuf[t2] = e;
            ssum += e;
        }
        sh_inv = 1.f / ssum;
    }
    __syncthreads();
    if (tid < TOPK)
        S[(size_t)row * N_TOTAL + idxbuf[tid]] = ebuf[tid] * sh_inv;

#undef PUSH
#undef EXACT_SELECT
#undef WARP_SELECT
}

// ===========================================================================
extern "C" void kernel_launch(void* const* d_in, const int* in_sizes, int n_in,
                              void* d_out, int out_size) {
    const float* inputs = (const float*)d_in[0];
    const float* W1     = (const float*)d_in[1];
    const float* b1     = (const float*)d_in[2];
    const float* gamma  = (const float*)d_in[3];
    const float* beta   = (const float*)d_in[4];
    const float* sw     = (const float*)d_in[5];
    const float* sb     = (const float*)d_in[6];

    float* outp = (float*)d_out;                       // [10000,128] outputs
    float* Sp   = outp + (size_t)N_TOTAL * D;          // [10000,10000] S

    cudaFuncSetAttribute(scores_kernel,
                         cudaFuncAttributeMaxDynamicSharedMemorySize, SC_SMEM);

    gemm1_kernel<<<(N_TOTAL + 31) / 32, 128>>>(inputs, W1, b1);
    bn_kernel<<<N_TOTAL / BSZ, D>>>(gamma, beta, sw, outp);
    scores_kernel<<<TRI_BLOCKS, 256, SC_SMEM>>>(outp, sb);
    topk_kernel<<<N_TOTAL, 256>>>(Sp);
}